// round 17
// baseline (speedup 1.0000x reference)
#include <cuda_runtime.h>
#include <cuda_bf16.h>
#include <cuda_fp16.h>
#include <math.h>
#include <stdint.h>

// ---------------- problem constants ----------------
#define BB   2
#define NN   10000
#define NT   20000           // BB*NN nodes
#define EE   160000          // edges per graph
#define EB   320000          // BB*EE batched edges
#define ET   340000          // EB + NT self loops
#define FIN  256
#define HID  256
#define HH   2
#define F1   512             // HH*HID
#define FOUT 256
#define NEG_SLOPE 0.2f

// ---------------- device scratch ----------------
__device__ __half g_xh1[(size_t)NT * F1];            // fp16 xw1 (gathers)
__device__ __half g_xh2[(size_t)NT * FOUT];          // fp16 xw2 (gathers)
__device__ __half g_A1h[(size_t)NT * FIN];           // fp16 x
__device__ __half g_A2h[(size_t)NT * F1];            // fp16 h (layer-2 GEMM input)
__device__ __half g_Wt1h[(size_t)512 * 256];         // W1^T fp16: [n=512][k=256]
__device__ __half g_Wt2h[(size_t)256 * 512];         // W2^T fp16: [n=256][k=512]
__device__ float g_v1[FIN * 4];                      // V1[k][4]: as_h0, ad_h0, as_h1, ad_h1
__device__ float g_v2s[F1];                          // V2 src
__device__ float g_v2d[F1];                          // V2 dst
__device__ float g_as1[NT * HH];
__device__ float g_ad1[NT * HH];
__device__ float g_as2[NT];
__device__ float g_ad2[NT];
__device__ int   g_cnt[NT + 1];
__device__ int   g_off[NT + 1];
__device__ int   g_srcidx[ET];

// ---------------- helpers ----------------
__device__ __forceinline__ uint32_t smem_u32(const void* p) {
    return (uint32_t)__cvta_generic_to_shared(p);
}
__device__ __forceinline__ void cp16(uint32_t dst, const void* src, int src_sz) {
    asm volatile("cp.async.cg.shared.global [%0], [%1], 16, %2;"
                 :: "r"(dst), "l"(src), "r"(src_sz) : "memory");
}
__device__ __forceinline__ void cp_commit() {
    asm volatile("cp.async.commit_group;" ::: "memory");
}
template <int N>
__device__ __forceinline__ void cp_wait() {
    asm volatile("cp.async.wait_group %0;" :: "n"(N) : "memory");
}
__device__ __forceinline__ void ldm4(uint32_t* r, uint32_t addr) {
    asm volatile("ldmatrix.sync.aligned.m8n8.x4.shared.b16 {%0,%1,%2,%3}, [%4];"
                 : "=r"(r[0]), "=r"(r[1]), "=r"(r[2]), "=r"(r[3]) : "r"(addr));
}
__device__ __forceinline__ void mma16816h(float* c, const uint32_t* a, const uint32_t* b) {
    asm volatile(
        "mma.sync.aligned.m16n8k16.row.col.f32.f16.f16.f32 "
        "{%0,%1,%2,%3}, {%4,%5,%6,%7}, {%8,%9}, {%0,%1,%2,%3};"
        : "+f"(c[0]), "+f"(c[1]), "+f"(c[2]), "+f"(c[3])
        : "r"(a[0]), "r"(a[1]), "r"(a[2]), "r"(a[3]), "r"(b[0]), "r"(b[1]));
}
// XOR swizzle: 64B rows, chunk' = chunk ^ ((row>>1)&3); conflict-free ldmatrix, 16B-aligned
__device__ __forceinline__ uint32_t swz(int row, int cByte) {
    return (uint32_t)(row * 64 + (cByte ^ ((((row >> 1) & 3)) << 4)));
}
__device__ __forceinline__ float lrelu(float e) {
    return e > 0.f ? e : NEG_SLOPE * e;
}
__device__ __forceinline__ void acc8(float* acc, const uint4& r, float ex) {
    float2 a0 = __half22float2(*(const __half2*)&r.x);
    float2 a1 = __half22float2(*(const __half2*)&r.y);
    float2 a2 = __half22float2(*(const __half2*)&r.z);
    float2 a3 = __half22float2(*(const __half2*)&r.w);
    acc[0] += ex * a0.x; acc[1] += ex * a0.y;
    acc[2] += ex * a1.x; acc[3] += ex * a1.y;
    acc[4] += ex * a2.x; acc[5] += ex * a2.y;
    acc[6] += ex * a3.x; acc[7] += ex * a3.y;
}

// ---------------- fp16 mma.sync GEMM, 4-stage cp.async, BKr=32, templated BN ----------------
#define BM 128
#define BKr 32
#define A_TILE_B (128 * 64)              // 8192 bytes (128 rows x 32 halfs, swizzled)
#define NSTG 4

template <int BNT>
__global__ __launch_bounds__(256, 2)
void gemm_kernel(const __half* __restrict__ A,
                 const __half* __restrict__ Bt,
                 __half* __restrict__ Ch, int M, int N, int K) {
    constexpr int B_TILE_B = BNT * 64;           // B tile bytes
    constexpr int STAGE_B = A_TILE_B + B_TILE_B;
    constexpr int NGRP = BNT / 32;               // 16-row B groups per warp tile
    constexpr int NFRG = BNT / 16;               // 8-col fragments per warp tile
    extern __shared__ char sm[];
    const int tid = threadIdx.x;
    const int lane = tid & 31;
    const int wid = tid >> 5;
    const int wm = wid & 3;                      // 4 warps over M (32 rows each)
    const int wn = wid >> 2;                     // 2 warps over N (BNT/2 cols each)
    const int m0 = blockIdx.y * BM;
    const int n0 = blockIdx.x * BNT;
    const uint32_t sbase = smem_u32(sm);

    float acc[2][NFRG][4];
#pragma unroll
    for (int i = 0; i < 2; i++)
#pragma unroll
        for (int j = 0; j < NFRG; j++)
#pragma unroll
            for (int t = 0; t < 4; t++) acc[i][j][t] = 0.f;

    const int lrow = tid >> 1;
    const int cb = (tid & 1) * 32;
    const uint32_t sw0 = swz(lrow, cb);
    const uint32_t sw1 = swz(lrow, cb + 16);
    const int ke = (tid & 1) * 16;
    const __half* gA = A + (size_t)(m0 + lrow) * K;
    const __half* gB = Bt + (size_t)(n0 + (lrow < BNT ? lrow : 0)) * K;
    const int a_ok = (m0 + lrow) < M ? 16 : 0;
    const bool b_do = lrow < BNT;

    const int NIT = K / BKr;

    auto issue = [&](int it) {
        const int s = it & (NSTG - 1);
        const int k0 = it * BKr + ke;
        uint32_t d = sbase + s * STAGE_B;
        cp16(d + sw0,            gA + k0,     a_ok);
        cp16(d + sw1,            gA + k0 + 8, a_ok);
        if (b_do) {
            cp16(d + A_TILE_B + sw0, gB + k0,     16);
            cp16(d + A_TILE_B + sw1, gB + k0 + 8, 16);
        }
        cp_commit();
    };

    issue(0); issue(1); issue(2);

    const int arow = wm * 32 + (lane & 15);
    const int acb = (lane >> 4) * 16;
    const int brow = wn * (BNT / 2) + (lane & 7) + ((lane >> 4) << 3);
    const int bcb = ((lane >> 3) & 1) * 16;

    for (int it = 0; it < NIT; it++) {
        const int s = it & (NSTG - 1);
        cp_wait<NSTG - 2>();
        __syncthreads();
        if (it + 3 < NIT) issue(it + 3); else cp_commit();

        const uint32_t base = sbase + s * STAGE_B;
#pragma unroll
        for (int k16 = 0; k16 < 2; k16++) {
            const int kc = acb + k16 * 32;
            uint32_t a[2][4];
#pragma unroll
            for (int mf = 0; mf < 2; mf++)
                ldm4(a[mf], base + swz(arow + mf * 16, kc));
            const int kb = bcb + k16 * 32;
#pragma unroll
            for (int ng = 0; ng < NGRP; ng++) {
                uint32_t b[4];
                ldm4(b, base + A_TILE_B + swz(brow + ng * 16, kb));
#pragma unroll
                for (int mf = 0; mf < 2; mf++) {
#pragma unroll
                    for (int t = 0; t < 2; t++)
                        mma16816h(acc[mf][ng * 2 + t], a[mf], b + 2 * t);
                }
            }
        }
    }

#pragma unroll
    for (int mf = 0; mf < 2; mf++) {
        const int mA = m0 + wm * 32 + mf * 16 + (lane >> 2);
        const int mB = mA + 8;
#pragma unroll
        for (int nf = 0; nf < NFRG; nf++) {
            const int n = n0 + wn * (BNT / 2) + nf * 8 + (lane & 3) * 2;
            const float* c = acc[mf][nf];
            if (mA < M) *(__half2*)(Ch + (size_t)mA * N + n) = __floats2half2_rn(c[0], c[1]);
            if (mB < M) *(__half2*)(Ch + (size_t)mB * N + n) = __floats2half2_rn(c[2], c[3]);
        }
    }
}

#define GEMM_SMEM_128 (NSTG * (A_TILE_B + 128 * 64))   // 65536
#define GEMM_SMEM_64  (NSTG * (A_TILE_B + 64 * 64))    // 49152

// ---------------- merged conversion kernel: x -> fp16, W1^T -> fp16 ----------------
#define CVX_N (NT * 128)           // half2 pairs of x
#define CVW1_N (512 * 256)
__global__ void conv_xw1_kernel(const float* __restrict__ x, const float* __restrict__ W1) {
    int i = blockIdx.x * blockDim.x + threadIdx.x;
    if (i < CVX_N) {
        int row = i >> 7;
        int c2 = (i & 127) << 1;
        float2 f = *(const float2*)(x + (size_t)row * FIN + c2);
        *(__half2*)(g_A1h + (size_t)row * FIN + c2) = __floats2half2_rn(f.x, f.y);
    } else {
        int k = i - CVX_N;
        if (k < CVW1_N) {
            int n = k >> 8, kk = k & 255;
            g_Wt1h[k] = __float2half(W1[(size_t)kk * F1 + n]);
        }
    }
}

__global__ void conv_w2_kernel(const float* __restrict__ W2) {
    int i = blockIdx.x * blockDim.x + threadIdx.x;   // over 256*512
    if (i >= 256 * 512) return;
    int n = i >> 9, k = i & 511;
    g_Wt2h[i] = __float2half(W2[(size_t)k * FOUT + n]);
}

// ---------------- fused attention vectors: V1 = W1 @ att1, V2 = W2 @ att2 ----------------
__global__ void vW1_kernel(const float* __restrict__ W1,
                           const float* __restrict__ as1, const float* __restrict__ ad1) {
    int k = (blockIdx.x * blockDim.x + threadIdx.x) >> 5;   // 256 warps
    int lane = threadIdx.x & 31;
    if (k >= FIN) return;
    const float* row = W1 + (size_t)k * F1;
    float p0 = 0.f, p1 = 0.f, p2 = 0.f, p3 = 0.f;
#pragma unroll
    for (int it = 0; it < 8; it++) {
        int c = lane + it * 32;
        float wa = row[c], wb = row[256 + c];
        p0 += wa * as1[c];         // head 0
        p1 += wa * ad1[c];
        p2 += wb * as1[256 + c];   // head 1
        p3 += wb * ad1[256 + c];
    }
#pragma unroll
    for (int o = 16; o > 0; o >>= 1) {
        p0 += __shfl_xor_sync(0xffffffffu, p0, o);
        p1 += __shfl_xor_sync(0xffffffffu, p1, o);
        p2 += __shfl_xor_sync(0xffffffffu, p2, o);
        p3 += __shfl_xor_sync(0xffffffffu, p3, o);
    }
    if (lane == 0) {
        g_v1[k * 4 + 0] = p0; g_v1[k * 4 + 1] = p1;
        g_v1[k * 4 + 2] = p2; g_v1[k * 4 + 3] = p3;
    }
}

__global__ void vW2_kernel(const float* __restrict__ W2,
                           const float* __restrict__ as2, const float* __restrict__ ad2) {
    int k = (blockIdx.x * blockDim.x + threadIdx.x) >> 5;   // 512 warps
    int lane = threadIdx.x & 31;
    if (k >= F1) return;
    const float* row = W2 + (size_t)k * FOUT;
    float p0 = 0.f, p1 = 0.f;
#pragma unroll
    for (int it = 0; it < 8; it++) {
        int c = lane + it * 32;
        float w = row[c];
        p0 += w * as2[c];
        p1 += w * ad2[c];
    }
#pragma unroll
    for (int o = 16; o > 0; o >>= 1) {
        p0 += __shfl_xor_sync(0xffffffffu, p0, o);
        p1 += __shfl_xor_sync(0xffffffffu, p1, o);
    }
    if (lane == 0) { g_v2s[k] = p0; g_v2d[k] = p1; }
}

// ---------------- alpha1 from raw x (fp32), forked stream ----------------
__global__ void alpha1_kernel(const float* __restrict__ x) {
    int gid = blockIdx.x * blockDim.x + threadIdx.x;
    int w = gid >> 5;
    int lane = gid & 31;
    if (w >= NT) return;
    const float* xr = x + (size_t)w * FIN;
    float p0 = 0.f, p1 = 0.f, p2 = 0.f, p3 = 0.f;
#pragma unroll
    for (int it = 0; it < 8; it++) {
        int c = lane + it * 32;
        float xv = xr[c];
        float4 v = *(const float4*)(g_v1 + c * 4);
        p0 += xv * v.x; p1 += xv * v.y; p2 += xv * v.z; p3 += xv * v.w;
    }
#pragma unroll
    for (int o = 16; o > 0; o >>= 1) {
        p0 += __shfl_xor_sync(0xffffffffu, p0, o);
        p1 += __shfl_xor_sync(0xffffffffu, p1, o);
        p2 += __shfl_xor_sync(0xffffffffu, p2, o);
        p3 += __shfl_xor_sync(0xffffffffu, p3, o);
    }
    if (lane == 0) {
        g_as1[w * 2 + 0] = p0; g_ad1[w * 2 + 0] = p1;
        g_as1[w * 2 + 1] = p2; g_ad1[w * 2 + 1] = p3;
    }
}

// ---------------- edge enumeration ----------------
__device__ __forceinline__ void edge_sd(int j, const int* ei, int& s, int& d) {
    if (j < EB) {
        int b = j / EE;
        int k = j - b * EE;
        s = ei[k]      + b * NN;
        d = ei[EE + k] + b * NN;
    } else {
        s = d = j - EB;
    }
}

// ---------------- CSR build (forked stream) ----------------
__global__ void zero_cnt_kernel() {
    int i = blockIdx.x * blockDim.x + threadIdx.x;
    if (i <= NT) g_cnt[i] = 0;
}

__global__ void count_kernel(const int* __restrict__ ei) {
    int j = blockIdx.x * blockDim.x + threadIdx.x;
    if (j >= ET) return;
    int s, d;
    edge_sd(j, ei, s, d);
    atomicAdd(&g_cnt[d], 1);
}

__global__ void scan_kernel() {
    __shared__ int warp_base[32];
    int t = threadIdx.x;
    int lane = t & 31, w = t >> 5;
    const int CH = 20;
    int base = t * CH;
    int local[CH];
    int sum = 0;
#pragma unroll
    for (int i = 0; i < CH; i++) {
        int idx = base + i;
        int v = (idx < NT) ? g_cnt[idx] : 0;
        local[i] = v;
        sum += v;
    }
    int inc = sum;
#pragma unroll
    for (int o = 1; o < 32; o <<= 1) {
        int v = __shfl_up_sync(0xffffffffu, inc, o);
        if (lane >= o) inc += v;
    }
    if (lane == 31) warp_base[w] = inc;
    __syncthreads();
    if (t < 32) {
        int v = warp_base[t];
        int wi = v;
#pragma unroll
        for (int o = 1; o < 32; o <<= 1) {
            int u = __shfl_up_sync(0xffffffffu, wi, o);
            if (t >= o) wi += u;
        }
        warp_base[t] = wi - v;
    }
    __syncthreads();
    int run = warp_base[w] + inc - sum;
#pragma unroll
    for (int i = 0; i < CH; i++) {
        int idx = base + i;
        if (idx < NT) { g_off[idx] = run; run += local[i]; }
    }
    if (t == 0) g_off[NT] = ET;
    for (int i = t; i < NT + 1; i += 1024) g_cnt[i] = 0;
}

__global__ void fill_kernel(const int* __restrict__ ei) {
    int j = blockIdx.x * blockDim.x + threadIdx.x;
    if (j >= ET) return;
    int s, d;
    edge_sd(j, ei, s, d);
    int pos = atomicAdd(&g_cnt[d], 1);
    g_srcidx[g_off[d] + pos] = s;
}

// ---------------- layer-1 aggregation: warp per dst, BOTH heads, prefetched; fused alpha2 ----------------
__global__ void agg1_kernel(const float* __restrict__ b1) {
    int d = (blockIdx.x * blockDim.x + threadIdx.x) >> 5;
    int lane = threadIdx.x & 31;
    if (d >= NT) return;
    int beg = g_off[d], end = g_off[d + 1];
    float2 ad = *(const float2*)(g_ad1 + d * 2);

    float acc0[8] = {0.f, 0.f, 0.f, 0.f, 0.f, 0.f, 0.f, 0.f};
    float acc1[8] = {0.f, 0.f, 0.f, 0.f, 0.f, 0.f, 0.f, 0.f};
    float den0 = 0.f, den1 = 0.f;
    int j = beg;
    int s0n = 0, s1n = 0;
    if (j + 1 < end) { s0n = g_srcidx[j]; s1n = g_srcidx[j + 1]; }
    for (; j + 1 < end; j += 2) {
        int s0 = s0n, s1 = s1n;
        if (j + 3 < end) { s0n = g_srcidx[j + 2]; s1n = g_srcidx[j + 3]; }
        float2 as0 = *(const float2*)(g_as1 + s0 * 2);
        float2 as1v = *(const float2*)(g_as1 + s1 * 2);
        const __half* p0 = g_xh1 + (size_t)s0 * F1 + lane * 8;
        const __half* p1 = g_xh1 + (size_t)s1 * F1 + lane * 8;
        uint4 rA0 = *(const uint4*)(p0);
        uint4 rB0 = *(const uint4*)(p0 + HID);
        uint4 rA1 = *(const uint4*)(p1);
        uint4 rB1 = *(const uint4*)(p1 + HID);
        float ex00 = __expf(lrelu(as0.x + ad.x));
        float ex01 = __expf(lrelu(as0.y + ad.y));
        float ex10 = __expf(lrelu(as1v.x + ad.x));
        float ex11 = __expf(lrelu(as1v.y + ad.y));
        den0 += ex00 + ex10;
        den1 += ex01 + ex11;
        acc8(acc0, rA0, ex00);
        acc8(acc1, rB0, ex01);
        acc8(acc0, rA1, ex10);
        acc8(acc1, rB1, ex11);
    }
    if (j < end) {
        int s0 = g_srcidx[j];
        float2 as0 = *(const float2*)(g_as1 + s0 * 2);
        const __half* p0 = g_xh1 + (size_t)s0 * F1 + lane * 8;
        uint4 rA0 = *(const uint4*)(p0);
        uint4 rB0 = *(const uint4*)(p0 + HID);
        float ex00 = __expf(lrelu(as0.x + ad.x));
        float ex01 = __expf(lrelu(as0.y + ad.y));
        den0 += ex00;
        den1 += ex01;
        acc8(acc0, rA0, ex00);
        acc8(acc1, rB0, ex01);
    }
    float inv0 = 1.f / (den0 + 1e-16f);
    float inv1 = 1.f / (den1 + 1e-16f);
    float v0[8], v1[8];
#pragma unroll
    for (int k = 0; k < 8; k++) {
        int c = lane * 8 + k;
        float t0 = acc0[k] * inv0 + b1[c];
        float t1 = acc1[k] * inv1 + b1[HID + c];
        v0[k] = 0.5f * t0 * (1.f + erff(t0 * 0.70710678118654752f));
        v1[k] = 0.5f * t1 * (1.f + erff(t1 * 0.70710678118654752f));
    }
    // ---- fused alpha2: h·V2 (h cols: head0 -> [lane*8..], head1 -> [256+lane*8..]) ----
    {
        float ps = 0.f, pd = 0.f;
#pragma unroll
        for (int k = 0; k < 8; k++) {
            int c = lane * 8 + k;
            ps += v0[k] * g_v2s[c] + v1[k] * g_v2s[HID + c];
            pd += v0[k] * g_v2d[c] + v1[k] * g_v2d[HID + c];
        }
#pragma unroll
        for (int o = 16; o > 0; o >>= 1) {
            ps += __shfl_xor_sync(0xffffffffu, ps, o);
            pd += __shfl_xor_sync(0xffffffffu, pd, o);
        }
        if (lane == 0) { g_as2[d] = ps; g_ad2[d] = pd; }
    }
    __half* outp = g_A2h + (size_t)d * F1 + lane * 8;
    uint4 pk0, pk1;
    {
        __half2 a = __floats2half2_rn(v0[0], v0[1]);
        __half2 b = __floats2half2_rn(v0[2], v0[3]);
        __half2 c = __floats2half2_rn(v0[4], v0[5]);
        __half2 e = __floats2half2_rn(v0[6], v0[7]);
        pk0.x = *(uint32_t*)&a; pk0.y = *(uint32_t*)&b;
        pk0.z = *(uint32_t*)&c; pk0.w = *(uint32_t*)&e;
        __half2 a1 = __floats2half2_rn(v1[0], v1[1]);
        __half2 b1h = __floats2half2_rn(v1[2], v1[3]);
        __half2 c1 = __floats2half2_rn(v1[4], v1[5]);
        __half2 e1 = __floats2half2_rn(v1[6], v1[7]);
        pk1.x = *(uint32_t*)&a1; pk1.y = *(uint32_t*)&b1h;
        pk1.z = *(uint32_t*)&c1; pk1.w = *(uint32_t*)&e1;
    }
    *(uint4*)(outp) = pk0;
    *(uint4*)(outp + HID) = pk1;
}

// ---------------- layer-2 aggregation: warp per dst, prefetched 4-edge unroll ----------------
__global__ void agg2_kernel(const float* __restrict__ b2, float* __restrict__ out) {
    int d = (blockIdx.x * blockDim.x + threadIdx.x) >> 5;
    int lane = threadIdx.x & 31;
    if (d >= NT) return;
    int beg = g_off[d], end = g_off[d + 1];
    float adh = g_ad2[d];

    float acc[8] = {0.f, 0.f, 0.f, 0.f, 0.f, 0.f, 0.f, 0.f};
    float denom = 0.f;
    int j = beg;
    int sn[4] = {0, 0, 0, 0};
    if (j + 3 < end) {
        sn[0] = g_srcidx[j];     sn[1] = g_srcidx[j + 1];
        sn[2] = g_srcidx[j + 2]; sn[3] = g_srcidx[j + 3];
    }
    for (; j + 3 < end; j += 4) {
        int s0 = sn[0], s1 = sn[1], s2 = sn[2], s3 = sn[3];
        if (j + 7 < end) {
            sn[0] = g_srcidx[j + 4]; sn[1] = g_srcidx[j + 5];
            sn[2] = g_srcidx[j + 6]; sn[3] = g_srcidx[j + 7];
        }
        float e0 = g_as2[s0] + adh;
        float e1 = g_as2[s1] + adh;
        float e2 = g_as2[s2] + adh;
        float e3 = g_as2[s3] + adh;
        uint4 r0 = *(const uint4*)(g_xh2 + (size_t)s0 * FOUT + lane * 8);
        uint4 r1 = *(const uint4*)(g_xh2 + (size_t)s1 * FOUT + lane * 8);
        uint4 r2 = *(const uint4*)(g_xh2 + (size_t)s2 * FOUT + lane * 8);
        uint4 r3 = *(const uint4*)(g_xh2 + (size_t)s3 * FOUT + lane * 8);
        float ex0 = __expf(lrelu(e0));
        float ex1 = __expf(lrelu(e1));
        float ex2 = __expf(lrelu(e2));
        float ex3 = __expf(lrelu(e3));
        denom += (ex0 + ex1) + (ex2 + ex3);
        acc8(acc, r0, ex0);
        acc8(acc, r1, ex1);
        acc8(acc, r2, ex2);
        acc8(acc, r3, ex3);
    }
    for (; j < end; j++) {
        int s0 = g_srcidx[j];
        float ex0 = __expf(lrelu(g_as2[s0] + adh));
        denom += ex0;
        uint4 r0 = *(const uint4*)(g_xh2 + (size_t)s0 * FOUT + lane * 8);
        acc8(acc, r0, ex0);
    }
    float inv = 1.f / (denom + 1e-16f);
    float* outp = out + (size_t)d * FOUT + lane * 8;
    float4 o0 = make_float4(acc[0] * inv + b2[lane * 8 + 0],
                            acc[1] * inv + b2[lane * 8 + 1],
                            acc[2] * inv + b2[lane * 8 + 2],
                            acc[3] * inv + b2[lane * 8 + 3]);
    float4 o1 = make_float4(acc[4] * inv + b2[lane * 8 + 4],
                            acc[5] * inv + b2[lane * 8 + 5],
                            acc[6] * inv + b2[lane * 8 + 6],
                            acc[7] * inv + b2[lane * 8 + 7]);
    *(float4*)(outp) = o0;
    *(float4*)(outp + 4) = o1;
}

// ---------------- launch ----------------
extern "C" void kernel_launch(void* const* d_in, const int* in_sizes, int n_in,
                              void* d_out, int out_size) {
    const float* x        = (const float*)d_in[0];
    const int*   ei       = (const int*)  d_in[1];
    const float* W1       = (const float*)d_in[2];
    const float* att_src1 = (const float*)d_in[3];
    const float* att_dst1 = (const float*)d_in[4];
    const float* b1       = (const float*)d_in[5];
    const float* W2       = (const float*)d_in[6];
    const float* att_src2 = (const float*)d_in[7];
    const float* att_dst2 = (const float*)d_in[8];
    const float* b2       = (const float*)d_in[9];
    float* out = (float*)d_out;

    __half *p_xh1, *p_xh2, *p_A1h, *p_A2h, *p_Wt1h, *p_Wt2h;
    cudaGetSymbolAddress((void**)&p_xh1,  g_xh1);
    cudaGetSymbolAddress((void**)&p_xh2,  g_xh2);
    cudaGetSymbolAddress((void**)&p_A1h,  g_A1h);
    cudaGetSymbolAddress((void**)&p_A2h,  g_A2h);
    cudaGetSymbolAddress((void**)&p_Wt1h, g_Wt1h);
    cudaGetSymbolAddress((void**)&p_Wt2h, g_Wt2h);

    static cudaStream_t s2 = nullptr;
    static cudaEvent_t evFork = nullptr, evJoin = nullptr;
    if (!s2) {
        cudaStreamCreateWithFlags(&s2, cudaStreamNonBlocking);
        cudaEventCreateWithFlags(&evFork, cudaEventDisableTiming);
        cudaEventCreateWithFlags(&evJoin, cudaEventDisableTiming);
        cudaFuncSetAttribute(gemm_kernel<128>, cudaFuncAttributeMaxDynamicSharedMemorySize, GEMM_SMEM_128);
        cudaFuncSetAttribute(gemm_kernel<64>,  cudaFuncAttributeMaxDynamicSharedMemorySize, GEMM_SMEM_64);
    }

    // ---- fork: CSR build + conv_w2 + fused att vectors + alpha1 on s2 ----
    cudaEventRecord(evFork, 0);
    cudaStreamWaitEvent(s2, evFork, 0);
    zero_cnt_kernel<<<(NT + 256) / 256, 256, 0, s2>>>();
    count_kernel<<<(ET + 255) / 256, 256, 0, s2>>>(ei);
    scan_kernel<<<1, 1024, 0, s2>>>();
    fill_kernel<<<(ET + 255) / 256, 256, 0, s2>>>(ei);
    conv_w2_kernel<<<(256 * 512 + 255) / 256, 256, 0, s2>>>(W2);
    vW1_kernel<<<(FIN * 32 + 255) / 256, 256, 0, s2>>>(W1, att_src1, att_dst1);
    vW2_kernel<<<(F1 * 32 + 255) / 256, 256, 0, s2>>>(W2, att_src2, att_dst2);
    alpha1_kernel<<<(NT * 32 + 255) / 256, 256, 0, s2>>>(x);
    cudaEventRecord(evJoin, s2);

    // ---- main: merged conversion + layer-1 GEMM ----
    conv_xw1_kernel<<<(CVX_N + CVW1_N + 255) / 256, 256>>>(x, W1);
    {
        dim3 grid(F1 / 128, (NT + BM - 1) / BM);
        gemm_kernel<128><<<grid, 256, GEMM_SMEM_128>>>(p_A1h, p_Wt1h, p_xh1, NT, F1, 256);
    }

    // ---- join fork, then aggregate (agg1 fuses alpha2) ----
    cudaStreamWaitEvent(0, evJoin, 0);
    agg1_kernel<<<(NT * 32 + 255) / 256, 256>>>(b1);

    // layer-2 GEMM (fp16, K=512, BN=64: 628 blocks, tight waves)
    {
        dim3 grid(FOUT / 64, (NT + BM - 1) / BM);
        gemm_kernel<64><<<grid, 256, GEMM_SMEM_64>>>(p_A2h, p_Wt2h, p_xh2, NT, FOUT, 512);
    }
    agg2_kernel<<<(NT * 32 + 255) / 256, 256>>>(b2, out);
}